// round 1
// baseline (speedup 1.0000x reference)
#include <cuda_runtime.h>
#include <cuda_bf16.h>

// Problem constants
#define BB   2
#define TT   4096
#define CC   768
#define HH   12
#define DH   64
#define BT   (BB*TT)          // 8192

// Scratch (device globals; allocation-free rule)
__device__ float g_q[BB*HH*TT*DH];   // [b*H+h][t][d]
__device__ float g_k[BB*HH*TT*DH];
__device__ float g_v[BB*HH*TT*DH];
__device__ float g_y[BT*CC];         // [b*T+t][c]

// ---------------------------------------------------------------------------
// GEMM (NT): out[r,c] = sum_k A[r,k] * W[c,k]
// Tile: 128(M) x 64(N), BK=16, 128 threads, 8x8 per thread.
// Column ownership split {tx*4 .. tx*4+3} U {tx*4+32 .. tx*4+35} -> conflict-free
// float4 smem loads in the inner loop.
// ---------------------------------------------------------------------------

__global__ void __launch_bounds__(128) qkv_gemm_kernel(
    const float* __restrict__ X,
    const float* __restrict__ Wq_,
    const float* __restrict__ Wk_,
    const float* __restrict__ Wv_)
{
    __shared__ float As[16][128];
    __shared__ float Bs[16][64];

    const int z  = blockIdx.z;
    const float* W = (z == 0) ? Wq_ : (z == 1) ? Wk_ : Wv_;
    float* dst     = (z == 0) ? g_q : (z == 1) ? g_k : g_v;

    const int cb = blockIdx.x;   // head index (64 cols == one head)
    const int rb = blockIdx.y;   // 0..63 (row tiles of 128)
    const int tid = threadIdx.x;
    const int tx = tid & 7;
    const int ty = tid >> 3;

    const float* Abase = X + (size_t)rb * 128 * CC;
    const float* Bbase = W + (size_t)cb * 64 * CC;

    float acc[8][8];
#pragma unroll
    for (int i = 0; i < 8; i++)
#pragma unroll
        for (int j = 0; j < 8; j++) acc[i][j] = 0.0f;

    const int mld = tid >> 2;           // 0..31
    const int k0  = (tid & 3) * 4;      // 0,4,8,12

    for (int kc = 0; kc < CC / 16; kc++) {
        const float* Ap = Abase + kc * 16;
#pragma unroll
        for (int l = 0; l < 4; l++) {
            int m = mld + l * 32;
            float4 v = *(const float4*)(Ap + (size_t)m * CC + k0);
            As[k0 + 0][m] = v.x; As[k0 + 1][m] = v.y;
            As[k0 + 2][m] = v.z; As[k0 + 3][m] = v.w;
        }
        const float* Bp = Bbase + kc * 16;
#pragma unroll
        for (int l = 0; l < 2; l++) {
            int n = mld + l * 32;
            float4 v = *(const float4*)(Bp + (size_t)n * CC + k0);
            Bs[k0 + 0][n] = v.x; Bs[k0 + 1][n] = v.y;
            Bs[k0 + 2][n] = v.z; Bs[k0 + 3][n] = v.w;
        }
        __syncthreads();
#pragma unroll
        for (int kk = 0; kk < 16; kk++) {
            float4 a0 = *(const float4*)&As[kk][ty * 8];
            float4 a1 = *(const float4*)&As[kk][ty * 8 + 4];
            float4 b0 = *(const float4*)&Bs[kk][tx * 4];
            float4 b1 = *(const float4*)&Bs[kk][tx * 4 + 32];
            float a[8] = {a0.x, a0.y, a0.z, a0.w, a1.x, a1.y, a1.z, a1.w};
            float b[8] = {b0.x, b0.y, b0.z, b0.w, b1.x, b1.y, b1.z, b1.w};
#pragma unroll
            for (int ii = 0; ii < 8; ii++)
#pragma unroll
                for (int jj = 0; jj < 8; jj++)
                    acc[ii][jj] += a[ii] * b[jj];
        }
        __syncthreads();
    }

    // Write to [b*H+h][t][d]; cols of this block == head cb, d == j.
#pragma unroll
    for (int ii = 0; ii < 8; ii++) {
        int r = rb * 128 + ty * 8 + ii;
        int b = r >> 12;
        int t = r & (TT - 1);
        float* drow = dst + ((size_t)(b * HH + cb) * TT + t) * DH;
        *(float4*)(drow + tx * 4) =
            make_float4(acc[ii][0], acc[ii][1], acc[ii][2], acc[ii][3]);
        *(float4*)(drow + tx * 4 + 32) =
            make_float4(acc[ii][4], acc[ii][5], acc[ii][6], acc[ii][7]);
    }
}

__global__ void __launch_bounds__(128) proj_gemm_kernel(
    const float* __restrict__ Wp,
    const float* __restrict__ bp,
    float* __restrict__ out)
{
    __shared__ float As[16][128];
    __shared__ float Bs[16][64];

    const int cb = blockIdx.x;
    const int rb = blockIdx.y;
    const int tid = threadIdx.x;
    const int tx = tid & 7;
    const int ty = tid >> 3;

    const float* Abase = g_y + (size_t)rb * 128 * CC;
    const float* Bbase = Wp + (size_t)cb * 64 * CC;

    float acc[8][8];
#pragma unroll
    for (int i = 0; i < 8; i++)
#pragma unroll
        for (int j = 0; j < 8; j++) acc[i][j] = 0.0f;

    const int mld = tid >> 2;
    const int k0  = (tid & 3) * 4;

    for (int kc = 0; kc < CC / 16; kc++) {
        const float* Ap = Abase + kc * 16;
#pragma unroll
        for (int l = 0; l < 4; l++) {
            int m = mld + l * 32;
            float4 v = *(const float4*)(Ap + (size_t)m * CC + k0);
            As[k0 + 0][m] = v.x; As[k0 + 1][m] = v.y;
            As[k0 + 2][m] = v.z; As[k0 + 3][m] = v.w;
        }
        const float* Bp = Bbase + kc * 16;
#pragma unroll
        for (int l = 0; l < 2; l++) {
            int n = mld + l * 32;
            float4 v = *(const float4*)(Bp + (size_t)n * CC + k0);
            Bs[k0 + 0][n] = v.x; Bs[k0 + 1][n] = v.y;
            Bs[k0 + 2][n] = v.z; Bs[k0 + 3][n] = v.w;
        }
        __syncthreads();
#pragma unroll
        for (int kk = 0; kk < 16; kk++) {
            float4 a0 = *(const float4*)&As[kk][ty * 8];
            float4 a1 = *(const float4*)&As[kk][ty * 8 + 4];
            float4 b0 = *(const float4*)&Bs[kk][tx * 4];
            float4 b1 = *(const float4*)&Bs[kk][tx * 4 + 32];
            float a[8] = {a0.x, a0.y, a0.z, a0.w, a1.x, a1.y, a1.z, a1.w};
            float b[8] = {b0.x, b0.y, b0.z, b0.w, b1.x, b1.y, b1.z, b1.w};
#pragma unroll
            for (int ii = 0; ii < 8; ii++)
#pragma unroll
                for (int jj = 0; jj < 8; jj++)
                    acc[ii][jj] += a[ii] * b[jj];
        }
        __syncthreads();
    }

    // bias
    float bv0[4], bv1[4];
#pragma unroll
    for (int q = 0; q < 4; q++) {
        bv0[q] = bp[cb * 64 + tx * 4 + q];
        bv1[q] = bp[cb * 64 + tx * 4 + 32 + q];
    }

#pragma unroll
    for (int ii = 0; ii < 8; ii++) {
        int r = rb * 128 + ty * 8 + ii;
        float* drow = out + (size_t)r * CC + cb * 64;
        *(float4*)(drow + tx * 4) =
            make_float4(acc[ii][0] + bv0[0], acc[ii][1] + bv0[1],
                        acc[ii][2] + bv0[2], acc[ii][3] + bv0[3]);
        *(float4*)(drow + tx * 4 + 32) =
            make_float4(acc[ii][4] + bv1[0], acc[ii][5] + bv1[1],
                        acc[ii][6] + bv1[2], acc[ii][7] + bv1[3]);
    }
}

// ---------------------------------------------------------------------------
// Flash attention (fp32, causal). BQ=128 queries per block, k-tiles of 64.
// 128 threads: tx=tid&7 (8 cols, split {tx*4, tx*4+32}), ty=tid>>3 (16 rows of 8).
// smem: Qs[d][i] 64x128 | Ks[d][j] 64x64 | Vs[j][d] 64x64 | Ps[j][i] 64x128 = 96KB
// ---------------------------------------------------------------------------

__global__ void __launch_bounds__(128) attn_kernel()
{
    extern __shared__ float sm[];
    float* Qs = sm;                 // [64][128] (Qs[d][i])
    float* Ks = Qs + 64 * 128;      // [64][64]  (Ks[d][j])
    float* Vs = Ks + 64 * 64;       // [64][64]  (Vs[j][d])
    float* Ps = Vs + 64 * 64;       // [64][128] (Ps[j][i])

    const int qt = (gridDim.x - 1) - blockIdx.x;   // heavy tiles first
    const int bh = blockIdx.y;
    const float* qb = g_q + (size_t)bh * TT * DH;
    const float* kb = g_k + (size_t)bh * TT * DH;
    const float* vb = g_v + (size_t)bh * TT * DH;

    const int tid = threadIdx.x;
    const int tx = tid & 7;
    const int ty = tid >> 3;

    // Load + transpose Q tile (pre-scaled by 1/sqrt(64))
#pragma unroll
    for (int l = 0; l < 16; l++) {
        int lin = (tid + l * 128) * 4;
        int i  = lin >> 6;        // 0..127
        int d0 = lin & 63;
        float4 v = *(const float4*)(qb + (size_t)(qt * 128 + i) * DH + d0);
        Qs[(d0 + 0) * 128 + i] = v.x * 0.125f;
        Qs[(d0 + 1) * 128 + i] = v.y * 0.125f;
        Qs[(d0 + 2) * 128 + i] = v.z * 0.125f;
        Qs[(d0 + 3) * 128 + i] = v.w * 0.125f;
    }

    float o[8][8];
    float mrow[8], lrow[8];
#pragma unroll
    for (int ii = 0; ii < 8; ii++) {
#pragma unroll
        for (int dd = 0; dd < 8; dd++) o[ii][dd] = 0.0f;
        mrow[ii] = -1e30f;
        lrow[ii] = 0.0f;
    }

    const int ktiles = 2 * qt + 2;
    for (int kt = 0; kt < ktiles; kt++) {
        __syncthreads();   // previous O-phase done reading Vs/Ps
        // load K (transposed) and V (natural)
#pragma unroll
        for (int l = 0; l < 8; l++) {
            int lin = (tid + l * 128) * 4;
            int j  = lin >> 6;       // 0..63
            int d0 = lin & 63;
            const float* kr = kb + (size_t)(kt * 64 + j) * DH + d0;
            float4 kv = *(const float4*)kr;
            Ks[(d0 + 0) * 64 + j] = kv.x;
            Ks[(d0 + 1) * 64 + j] = kv.y;
            Ks[(d0 + 2) * 64 + j] = kv.z;
            Ks[(d0 + 3) * 64 + j] = kv.w;
            const float* vr = vb + (size_t)(kt * 64 + j) * DH + d0;
            *(float4*)(Vs + j * 64 + d0) = *(const float4*)vr;
        }
        __syncthreads();

        // S = Q K^T
        float s[8][8];
#pragma unroll
        for (int ii = 0; ii < 8; ii++)
#pragma unroll
            for (int jj = 0; jj < 8; jj++) s[ii][jj] = 0.0f;

#pragma unroll 8
        for (int d = 0; d < 64; d++) {
            float4 a0 = *(const float4*)(Qs + d * 128 + ty * 8);
            float4 a1 = *(const float4*)(Qs + d * 128 + ty * 8 + 4);
            float4 b0 = *(const float4*)(Ks + d * 64 + tx * 4);
            float4 b1 = *(const float4*)(Ks + d * 64 + tx * 4 + 32);
            float a[8] = {a0.x, a0.y, a0.z, a0.w, a1.x, a1.y, a1.z, a1.w};
            float b[8] = {b0.x, b0.y, b0.z, b0.w, b1.x, b1.y, b1.z, b1.w};
#pragma unroll
            for (int ii = 0; ii < 8; ii++)
#pragma unroll
                for (int jj = 0; jj < 8; jj++)
                    s[ii][jj] += a[ii] * b[jj];
        }

        // causal mask (only near the diagonal)
        if (kt >= 2 * qt) {
#pragma unroll
            for (int ii = 0; ii < 8; ii++) {
                int iq = qt * 128 + ty * 8 + ii;
#pragma unroll
                for (int jj = 0; jj < 8; jj++) {
                    int jk = kt * 64 + tx * 4 + (jj & 3) + ((jj >> 2) << 5);
                    if (jk > iq) s[ii][jj] = -1e30f;
                }
            }
        }

        // online softmax
#pragma unroll
        for (int ii = 0; ii < 8; ii++) {
            float tmax = s[ii][0];
#pragma unroll
            for (int jj = 1; jj < 8; jj++) tmax = fmaxf(tmax, s[ii][jj]);
            tmax = fmaxf(tmax, __shfl_xor_sync(0xffffffffu, tmax, 1));
            tmax = fmaxf(tmax, __shfl_xor_sync(0xffffffffu, tmax, 2));
            tmax = fmaxf(tmax, __shfl_xor_sync(0xffffffffu, tmax, 4));
            float mnew = fmaxf(mrow[ii], tmax);
            float alpha = __expf(mrow[ii] - mnew);
            mrow[ii] = mnew;
            float rsum = 0.0f;
#pragma unroll
            for (int jj = 0; jj < 8; jj++) {
                float p = __expf(s[ii][jj] - mnew);
                s[ii][jj] = p;
                rsum += p;
            }
            rsum += __shfl_xor_sync(0xffffffffu, rsum, 1);
            rsum += __shfl_xor_sync(0xffffffffu, rsum, 2);
            rsum += __shfl_xor_sync(0xffffffffu, rsum, 4);
            lrow[ii] = lrow[ii] * alpha + rsum;
#pragma unroll
            for (int dd = 0; dd < 8; dd++) o[ii][dd] *= alpha;
        }

        // stage P (transposed) to smem
#pragma unroll
        for (int jj = 0; jj < 8; jj++) {
            int j = tx * 4 + (jj & 3) + ((jj >> 2) << 5);
#pragma unroll
            for (int ii = 0; ii < 8; ii++)
                Ps[j * 128 + ty * 8 + ii] = s[ii][jj];
        }
        __syncthreads();

        // O += P V
#pragma unroll 8
        for (int j = 0; j < 64; j++) {
            float4 p0 = *(const float4*)(Ps + j * 128 + ty * 8);
            float4 p1 = *(const float4*)(Ps + j * 128 + ty * 8 + 4);
            float4 v0 = *(const float4*)(Vs + j * 64 + tx * 4);
            float4 v1 = *(const float4*)(Vs + j * 64 + tx * 4 + 32);
            float p[8] = {p0.x, p0.y, p0.z, p0.w, p1.x, p1.y, p1.z, p1.w};
            float v[8] = {v0.x, v0.y, v0.z, v0.w, v1.x, v1.y, v1.z, v1.w};
#pragma unroll
            for (int ii = 0; ii < 8; ii++)
#pragma unroll
                for (int dd = 0; dd < 8; dd++)
                    o[ii][dd] += p[ii] * v[dd];
        }
    }

    // finalize: write to g_y[b*T+t][h*64+d]
    const int b = bh / HH;
    const int h = bh % HH;
#pragma unroll
    for (int ii = 0; ii < 8; ii++) {
        float inv = 1.0f / lrow[ii];
        int t = qt * 128 + ty * 8 + ii;
        float* drow = g_y + (size_t)(b * TT + t) * CC + h * DH;
        *(float4*)(drow + tx * 4) =
            make_float4(o[ii][0] * inv, o[ii][1] * inv,
                        o[ii][2] * inv, o[ii][3] * inv);
        *(float4*)(drow + tx * 4 + 32) =
            make_float4(o[ii][4] * inv, o[ii][5] * inv,
                        o[ii][6] * inv, o[ii][7] * inv);
    }
}

// ---------------------------------------------------------------------------

extern "C" void kernel_launch(void* const* d_in, const int* in_sizes, int n_in,
                              void* d_out, int out_size)
{
    const float* x  = (const float*)d_in[0];
    const float* Wk = (const float*)d_in[1];
    const float* Wq = (const float*)d_in[2];
    const float* Wv = (const float*)d_in[3];
    const float* Wp = (const float*)d_in[4];
    const float* bp = (const float*)d_in[5];
    float* out = (float*)d_out;

    // QKV projections: grid (heads=12, row-tiles=64, z=3 for q/k/v)
    qkv_gemm_kernel<<<dim3(12, 64, 3), 128>>>(x, Wq, Wk, Wv);

    // Flash attention: grid (q-tiles=32, b*h=24), 96KB dynamic smem
    const int attn_smem = 24576 * sizeof(float);   // 96KB
    cudaFuncSetAttribute(attn_kernel,
                         cudaFuncAttributeMaxDynamicSharedMemorySize, attn_smem);
    attn_kernel<<<dim3(32, 24), 128, attn_smem>>>();

    // Output projection + bias
    proj_gemm_kernel<<<dim3(12, 64), 128>>>(Wp, bp, out);
}